// round 8
// baseline (speedup 1.0000x reference)
#include <cuda_runtime.h>
#include <cstdint>

// STC_LIF recurrence, exact-fp32 sparse formulation.
// R8: fixed-16-slot fully-unrolled compaction gather. Lanes rank their spike
// bits via popc-prefix and scatter active k-indices (ascending) into a
// per-warp buffer; lanes<16 write sentinel k=128 (zeros row in smem W) at
// cb[cnt+lane], covering every padded slot of both the fixed 16-slot unrolled
// body and the rare (cnt>16, ~1%) dynamic tail. Trailing +0.0 adds are exact
// no-ops; per-element FADD order identical to the rel_err=0.0 R2 kernel.

#define NSTEP 512
#define BATCH 1024
#define DIM 128
#define WARPS_PER_CTA 8
#define NCTAS (BATCH / WARPS_PER_CTA)        // 128
#define NTHREADS (WARPS_PER_CTA * 32)        // 256
#define W_KENT 129                            // k = 0..127 real, k = 128 zeros
#define SMEM_W_BYTES (W_KENT * 32 * 16)       // 66048
#define CBUF_U32 144                          // cnt(<=128) + 16 sentinels
#define SMEM_CBUF_BYTES (WARPS_PER_CTA * 2 * CBUF_U32 * 4)   // 9216
#define SMEM_BYTES (SMEM_W_BYTES + SMEM_CBUF_BYTES)

// XLA / Eigen fast tanh for f32 (matches jnp.tanh lowering; verified exact).
__device__ __forceinline__ float xla_tanh(float x) {
    float cx = fmaxf(fminf(x, 7.90531110763549805f), -7.90531110763549805f);
    float x2 = __fmul_rn(cx, cx);
    float p = __fmaf_rn(x2, -2.76076847742355e-16f, 2.00018790482477e-13f);
    p = __fmaf_rn(x2, p, -8.60467152213735e-11f);
    p = __fmaf_rn(x2, p, 5.12229709037114e-08f);
    p = __fmaf_rn(x2, p, 1.48572235717979e-05f);
    p = __fmaf_rn(x2, p, 6.37261928875436e-04f);
    p = __fmaf_rn(x2, p, 4.89352455891786e-03f);
    p = __fmul_rn(cx, p);
    float q = __fmaf_rn(x2, 1.19825839466702e-06f, 1.18534705686654e-04f);
    q = __fmaf_rn(x2, q, 2.26843463243900e-03f);
    q = __fmaf_rn(x2, q, 4.89352518554385e-03f);
    float t = __fdiv_rn(p, q);
    return (fabsf(x) < 0.0004f) ? x : t;
}

// Accumulate 4 slots (one uint4 of k-indices) in ascending slot order.
#define ACC_CHUNK(id)                                                   \
    do {                                                                \
        float4 _a = *(const float4*)(Wlb + (id).x * 512);               \
        float4 _b = *(const float4*)(Wlb + (id).y * 512);               \
        float4 _c = *(const float4*)(Wlb + (id).z * 512);               \
        float4 _d = *(const float4*)(Wlb + (id).w * 512);               \
        z0 = __fadd_rn(z0, _a.x); z1 = __fadd_rn(z1, _a.y);             \
        z2 = __fadd_rn(z2, _a.z); z3 = __fadd_rn(z3, _a.w);             \
        z0 = __fadd_rn(z0, _b.x); z1 = __fadd_rn(z1, _b.y);             \
        z2 = __fadd_rn(z2, _b.z); z3 = __fadd_rn(z3, _b.w);             \
        z0 = __fadd_rn(z0, _c.x); z1 = __fadd_rn(z1, _c.y);             \
        z2 = __fadd_rn(z2, _c.z); z3 = __fadd_rn(z3, _c.w);             \
        z0 = __fadd_rn(z0, _d.x); z1 = __fadd_rn(z1, _d.y);             \
        z2 = __fadd_rn(z2, _d.z); z3 = __fadd_rn(z3, _d.w);             \
    } while (0)

__global__ void __launch_bounds__(NTHREADS, 1)
stc_lif_kernel(const float* __restrict__ x,
               const float* __restrict__ mem0,
               const float* __restrict__ sp0,
               const float* __restrict__ W,      // [D, D], z[d] = sum_k s[k]*W[d,k]
               const float* __restrict__ bias,   // [D]
               float* __restrict__ out)
{
    // WTp[k*32 + l] is a float4 whose component c holds W[(32c + l)*DIM + k];
    // entry k=128 is all zeros (sentinel target for padded slots).
    extern __shared__ unsigned char smem_raw[];
    float4*   WTp  = (float4*)smem_raw;
    unsigned* cbuf = (unsigned*)(smem_raw + SMEM_W_BYTES);

    const int tid  = threadIdx.x;
    const int lane = tid & 31;
    const int warp = tid >> 5;
    const int row  = blockIdx.x * WARPS_PER_CTA + warp;   // 0..1023

    for (int e = tid; e < W_KENT * 32; e += NTHREADS) {
        int k = e >> 5, l = e & 31;
        float4 v;
        if (k < DIM) {
            v.x = W[(l      ) * DIM + k];
            v.y = W[(32 + l ) * DIM + k];
            v.z = W[(64 + l ) * DIM + k];
            v.w = W[(96 + l ) * DIM + k];
        } else {
            v = make_float4(0.0f, 0.0f, 0.0f, 0.0f);
        }
        WTp[e] = v;
    }
    __syncthreads();

    const float b0 = bias[lane], b1 = bias[32 + lane],
                b2 = bias[64 + lane], b3 = bias[96 + lane];

    const float* mrow = mem0 + (size_t)row * DIM;
    float m0 = mrow[lane], m1 = mrow[32 + lane],
          m2 = mrow[64 + lane], m3 = mrow[96 + lane];

    // Spike flags for this lane's 4 dims (k = lane, 32+lane, 64+lane, 96+lane)
    const float* srow = sp0 + (size_t)row * DIM;
    bool f0 = srow[lane]      != 0.0f;
    bool f1 = srow[32 + lane] != 0.0f;
    bool f2 = srow[64 + lane] != 0.0f;
    bool f3 = srow[96 + lane] != 0.0f;
    unsigned w0 = __ballot_sync(0xffffffffu, f0);
    unsigned w1 = __ballot_sync(0xffffffffu, f1);
    unsigned w2 = __ballot_sync(0xffffffffu, f2);
    unsigned w3 = __ballot_sync(0xffffffffu, f3);

    const size_t step_stride = (size_t)BATCH * DIM;       // 131072
    const float* xp = x   + (size_t)row * DIM + lane;
    float*       op = out + (size_t)row * DIM + lane;

    float xa0 = xp[0], xa1 = xp[32], xa2 = xp[64], xa3 = xp[96];

    const unsigned mlt = (1u << lane) - 1u;               // lanemask_lt
    const char* Wlb = (const char*)(WTp + lane);          // +k*512 bytes per k
    unsigned* cb_base = cbuf + warp * 2 * CBUF_U32;

    for (int i = 0; i < NSTEP; i++) {
        const float* xq = (i + 1 < NSTEP) ? (xp + step_stride) : xp;
        float xn0 = xq[0], xn1 = xq[32], xn2 = xq[64], xn3 = xq[96];

        // ---- compaction: ranks of this lane's active k's (ascending) ----
        unsigned* cb = cb_base + (i & 1) * CBUF_U32;
        unsigned r0   = __popc(w0 & mlt);
        unsigned c0   = __popc(w0);
        unsigned r1   = c0 + __popc(w1 & mlt);
        unsigned c01  = c0 + __popc(w1);
        unsigned r2   = c01 + __popc(w2 & mlt);
        unsigned c012 = c01 + __popc(w2);
        unsigned r3   = c012 + __popc(w3 & mlt);
        unsigned cnt  = c012 + __popc(w3);

        // Sentinels first cover every slot in [cnt, cnt+16): all pads of the
        // fixed 16-slot body (cnt < 16) and of the rare tail's last chunk.
        if (lane < 16) cb[cnt + lane] = 128u;
        if (f0) cb[r0] = (unsigned)lane;
        if (f1) cb[r1] = (unsigned)(32 + lane);
        if (f2) cb[r2] = (unsigned)(64 + lane);
        if (f3) cb[r3] = (unsigned)(96 + lane);
        __syncwarp();

        // ---- z[d] = ascending-k sparse sum; pads add exact +0.0 ----
        // Fixed 16 slots, fully unrolled: 4 id-LDS.128 then 16 W-LDS.128
        // issue back-to-back (deep MLP), no loop branches.
        float z0 = 0.0f, z1 = 0.0f, z2 = 0.0f, z3 = 0.0f;
        const uint4* cb4 = (const uint4*)cb;
        {
            uint4 i0 = cb4[0], i1 = cb4[1], i2 = cb4[2], i3 = cb4[3];
            ACC_CHUNK(i0);
            ACC_CHUNK(i1);
            ACC_CHUNK(i2);
            ACC_CHUNK(i3);
        }
        if (cnt > 16) {                        // ~1% of steps: dynamic tail
            for (unsigned j = 16; j < cnt; j += 4) {
                uint4 id = cb4[j >> 2];
                ACC_CHUNK(id);
            }
        }

        // gamma = (1 + tanh(z + b)) * 0.5   (unfused, XLA rounding)
        float t0 = xla_tanh(__fadd_rn(z0, b0));
        float t1 = xla_tanh(__fadd_rn(z1, b1));
        float t2 = xla_tanh(__fadd_rn(z2, b2));
        float t3 = xla_tanh(__fadd_rn(z3, b3));
        float g0 = __fmul_rn(__fadd_rn(1.0f, t0), 0.5f);
        float g1 = __fmul_rn(__fadd_rn(1.0f, t1), 0.5f);
        float g2 = __fmul_rn(__fadd_rn(1.0f, t2), 0.5f);
        float g3 = __fmul_rn(__fadd_rn(1.0f, t3), 0.5f);

        // m = m + x * gamma  (mul then add, unfused)
        m0 = __fadd_rn(m0, __fmul_rn(xa0, g0));
        m1 = __fadd_rn(m1, __fmul_rn(xa1, g1));
        m2 = __fadd_rn(m2, __fmul_rn(xa2, g2));
        m3 = __fadd_rn(m3, __fmul_rn(xa3, g3));

        // spike = (m >= 1); reset m to 0 on spike (== m*(1-s), exact)
        f0 = (m0 >= 1.0f); f1 = (m1 >= 1.0f); f2 = (m2 >= 1.0f); f3 = (m3 >= 1.0f);

        w0 = __ballot_sync(0xffffffffu, f0);
        w1 = __ballot_sync(0xffffffffu, f1);
        w2 = __ballot_sync(0xffffffffu, f2);
        w3 = __ballot_sync(0xffffffffu, f3);

        m0 = f0 ? 0.0f : m0;  m1 = f1 ? 0.0f : m1;
        m2 = f2 ? 0.0f : m2;  m3 = f3 ? 0.0f : m3;

        op[0]  = f0 ? 1.0f : 0.0f;
        op[32] = f1 ? 1.0f : 0.0f;
        op[64] = f2 ? 1.0f : 0.0f;
        op[96] = f3 ? 1.0f : 0.0f;

        xa0 = xn0; xa1 = xn1; xa2 = xn2; xa3 = xn3;
        xp += step_stride;
        op += step_stride;
    }
}

extern "C" void kernel_launch(void* const* d_in, const int* in_sizes, int n_in,
                              void* d_out, int out_size)
{
    (void)in_sizes; (void)n_in; (void)out_size;
    const float* x    = (const float*)d_in[0];
    const float* mem0 = (const float*)d_in[1];
    const float* sp0  = (const float*)d_in[2];
    const float* Wgs  = (const float*)d_in[3];
    const float* bgs  = (const float*)d_in[4];
    // d_in[5], d_in[6] (W_gt_w, W_gt_b) are dead in the reference's 3D branch.
    float* out = (float*)d_out;

    (void)cudaFuncSetAttribute(stc_lif_kernel,
                               cudaFuncAttributeMaxDynamicSharedMemorySize,
                               SMEM_BYTES);
    stc_lif_kernel<<<NCTAS, NTHREADS, SMEM_BYTES>>>(x, mem0, sp0, Wgs, bgs, out);
}